// round 14
// baseline (speedup 1.0000x reference)
#include <cuda_runtime.h>
#include <cuda_bf16.h>
#include <cstdint>

#define SEQ   600
#define BATCH 4096
#define INP   6
#define HID   30
#define OUTD  61
#define NB    32               // batches per CTA (GEMM M)
#define NBLK  (BATCH / NB)     // 128 CTAs
#define NTHR  512              // 16 warps
#define BST   104              // v-row byte stride in sB (bank-spread, 8B mult)
#define SBB   (NB * BST)       // 3328 B per (buf, term)

typedef unsigned long long ull;
typedef uint32_t u32;

// ---------------- device globals ----------------
// weight B-fragments: [wN][ntile][ktile][term][lane][j]  (j: b0/b1)
__device__ u32  g_Bfrag[8][2][3][2][32][2];
__device__ float g_M[HID][OUTD];     // fused fc1+fc2
__device__ float g_bv[OUTD];

// ---------------- helpers ----------------
__device__ __forceinline__ float tanh_fast(float x) {
    float r; asm("tanh.approx.f32 %0, %1;" : "=f"(r) : "f"(x)); return r;
}
__device__ __forceinline__ float sigmoid_fast(float x) {
    return fmaf(0.5f, tanh_fast(0.5f * x), 0.5f);
}
__device__ __forceinline__ u32 pack_bf16x2(float lo_k, float hi_k) {
    __nv_bfloat162 p = __floats2bfloat162_rn(lo_k, hi_k);   // .x = first elem (lower k)
    return *(u32*)&p;
}
// byte offset of k-value within one batch's v-row (slot layout: one ull slot
// s = kt*4+tig holds pairs (p, p+4), p = k/2 -> LDS.64 = one A-frag reg pair)
__device__ __host__ __forceinline__ u32 koff(int k) {
    int p = k >> 1, kt = p >> 3, q = p & 7;
    return (u32)(((kt << 2) + (q & 3)) * 8 + (q >> 2) * 4 + (k & 1) * 2);
}

__device__ __forceinline__ void mma16816(float* d, const u32* a, const u32* b) {
    asm volatile(
        "mma.sync.aligned.m16n8k16.row.col.f32.bf16.bf16.f32 "
        "{%0,%1,%2,%3}, {%4,%5,%6,%7}, {%8,%9}, {%0,%1,%2,%3};"
        : "+f"(d[0]), "+f"(d[1]), "+f"(d[2]), "+f"(d[3])
        : "r"(a[0]), "r"(a[1]), "r"(a[2]), "r"(a[3]), "r"(b[0]), "r"(b[1]));
}

// ---------------- prep kernel ----------------
__device__ __forceinline__ float Wval(const float* Wih, const float* Whh,
                                      const float* bih, const float* bhh, int r, int k) {
    int u = r >> 2, g = r & 3;
    if (u >= HID) return 0.0f;
    if (k < HID)       return Whh[(g * HID + u) * HID + k];
    if (k < HID + INP) return Wih[(g * HID + u) * INP + (k - HID)];
    if (k == 36)       return bih[g * HID + u] + bhh[g * HID + u];
    return 0.0f;
}

__global__ void prep_kernel(const float* __restrict__ Wih, const float* __restrict__ Whh,
                            const float* __restrict__ bih, const float* __restrict__ bhh,
                            const float* __restrict__ W1,  const float* __restrict__ b1,
                            const float* __restrict__ W2,  const float* __restrict__ b2) {
    int tid = threadIdx.x;
    for (int idx = tid; idx < 8 * 2 * 3 * 2 * 32 * 2; idx += blockDim.x) {
        int j    = idx & 1;
        int lane = (idx >> 1) & 31;
        int tm   = (idx >> 6) & 1;
        int kt   = (idx >> 7) % 3;
        int nt   = (idx >> 7) / 3 & 1;
        int w    = idx / (2 * 3 * 2 * 32 * 2);
        int g0 = lane >> 2, tig = lane & 3;
        int r = 16 * w + 8 * nt + g0;
        int k = 2 * tig + 16 * kt + 8 * j;
        float w0 = Wval(Wih, Whh, bih, bhh, r, k);
        float w1 = Wval(Wih, Whh, bih, bhh, r, k + 1);
        float h0 = __bfloat162float(__float2bfloat16(w0));
        float h1 = __bfloat162float(__float2bfloat16(w1));
        u32 v = (tm == 0) ? pack_bf16x2(h0, h1) : pack_bf16x2(w0 - h0, w1 - h1);
        g_Bfrag[w][nt][kt][tm][lane][j] = v;
    }
    for (int idx = tid; idx < HID * OUTD; idx += blockDim.x) {
        int j = idx / OUTD, o = idx % OUTD;
        float s = 0.0f;
        for (int kk = 0; kk < HID; kk++) s += W1[kk * HID + j] * W2[o * HID + kk];
        g_M[j][o] = s;
    }
    for (int o = tid; o < OUTD; o += blockDim.x) {
        float s = b2[o];
        for (int kk = 0; kk < HID; kk++) s += b1[kk] * W2[o * HID + kk];
        g_bv[o] = s;
    }
}

// ---------------- main kernel: 3xBF16 mma.sync, 16 warps ----------------
__global__ void __launch_bounds__(NTHR, 1)
lstm_kernel(const float* __restrict__ X, float* __restrict__ out) {
    // v = [h|x|bias] as bf16, hi/lo terms, double-buffered
    __shared__ __align__(16) char sB[2][2][SBB];   // 13312 B

    const int tid   = threadIdx.x;
    const int lane  = tid & 31;
    const int wid   = tid >> 5;            // 0..15
    const int wN    = wid & 7;             // gate-row group: rows 16wN..16wN+15
    const int dm    = wid >> 3;            // m-tile: batches 16dm..16dm+15
    const int g0    = lane >> 2;
    const int tig   = lane & 3;
    const int bbase = blockIdx.x * NB;

    // persistent weight fragments for my gate-rows
    u32 Bf[2][3][2][2];
#pragma unroll
    for (int nt = 0; nt < 2; nt++)
#pragma unroll
        for (int kt = 0; kt < 3; kt++)
#pragma unroll
            for (int tm = 0; tm < 2; tm++) {
                Bf[nt][kt][tm][0] = g_Bfrag[wN][nt][kt][tm][lane][0];
                Bf[nt][kt][tm][1] = g_Bfrag[wN][nt][kt][tm][lane][1];
            }

    // init: zero both buffers, set bias col (k=36 -> byte 80) in hi term
    for (int i = tid; i < 2 * 2 * SBB / 4; i += NTHR) ((u32*)sB)[i] = 0u;
    __syncthreads();
    if (tid < NB) {
        *(u32*)(&sB[0][0][tid * BST + 80]) = 0x00003F80u;   // {bf16(1.0), 0}
        *(u32*)(&sB[1][0][tid * BST + 80]) = 0x00003F80u;
    }
    // stage x(0) into buf 0
    const int bx = tid & 31, jx = tid >> 5;   // tid<96: batch bx, x-pair jx
    if (tid < 96) {
        float2 xv = *(const float2*)(X + ((size_t)bbase + bx) * INP + 2 * jx);
        float h0 = __bfloat162float(__float2bfloat16(xv.x));
        float h1 = __bfloat162float(__float2bfloat16(xv.y));
        *(u32*)(&sB[0][0][bx * BST + koff(30 + 2 * jx)]) = pack_bf16x2(h0, h1);
        *(u32*)(&sB[0][1][bx * BST + koff(30 + 2 * jx)]) = pack_bf16x2(xv.x - h0, xv.y - h1);
    }
    __syncthreads();

    // per-lane epilogue identity
    const int myu  = 4 * wN + (tig >> 1);    // + 2*nt
    const int myb  = g0 + 8 * (tig & 1) + 16 * dm;
    const int odd  = tig & 1;

    float cst[2] = {0.0f, 0.0f};

#pragma unroll 1
    for (int t = 0; t < SEQ; ++t) {
        const int bt = t & 1, nb = bt ^ 1;

        // prefetch x(t+1)
        float2 xv = make_float2(0.0f, 0.0f);
        const int tn = (t + 1 < SEQ) ? t + 1 : t;
        if (tid < 96)
            xv = *(const float2*)(X + ((size_t)tn * BATCH + bbase + bx) * INP + 2 * jx);

        // ---- load A fragments (my m-tile only): one LDS.64 = {a_klo, a_khi} ----
        u32 A[3][2][4];
#pragma unroll
        for (int kt = 0; kt < 3; kt++)
#pragma unroll
            for (int tm = 0; tm < 2; tm++) {
                const char* base = sB[bt][tm];
                ull v0 = *(const ull*)(base + (16 * dm + g0) * BST + (kt * 4 + tig) * 8);
                ull v1 = *(const ull*)(base + (16 * dm + g0 + 8) * BST + (kt * 4 + tig) * 8);
                A[kt][tm][0] = (u32)v0;  A[kt][tm][2] = (u32)(v0 >> 32);
                A[kt][tm][1] = (u32)v1;  A[kt][tm][3] = (u32)(v1 >> 32);
            }

        // ---- 18 mma: 2 D tiles (nt), each split into 2 accumulators ----
        float D[2][4], E[2][4];
#pragma unroll
        for (int nt = 0; nt < 2; nt++) {
            D[nt][0] = D[nt][1] = D[nt][2] = D[nt][3] = 0.0f;
            E[nt][0] = E[nt][1] = E[nt][2] = E[nt][3] = 0.0f;
#pragma unroll
            for (int kt = 0; kt < 3; kt++) {
                mma16816(D[nt], A[kt][0], Bf[nt][kt][0]);  // vhi*whi
                mma16816(E[nt], A[kt][0], Bf[nt][kt][1]);  // vhi*wlo
                mma16816(D[nt], A[kt][1], Bf[nt][kt][0]);  // vlo*whi
            }
#pragma unroll
            for (int i = 0; i < 4; i++) D[nt][i] += E[nt][i];
        }

        // ---- epilogue: gates via shfl.xor(1), act, c/h update, h store ----
#pragma unroll
        for (int nt = 0; nt < 2; nt++) {
            float d0 = D[nt][0], d1 = D[nt][1];
            float d2 = D[nt][2], d3 = D[nt][3];
            float s0 = __shfl_xor_sync(0xffffffffu, d0, 1);
            float s1 = __shfl_xor_sync(0xffffffffu, d1, 1);
            float s2 = __shfl_xor_sync(0xffffffffu, d2, 1);
            float s3 = __shfl_xor_sync(0xffffffffu, d3, 1);
            float gi = odd ? s2 : d0;
            float gf = odd ? s3 : d1;
            float gg = odd ? d2 : s0;
            float go = odd ? d3 : s1;
            float si = sigmoid_fast(gi);
            float sf = sigmoid_fast(gf);
            float tg = tanh_fast(gg);
            float so = sigmoid_fast(go);
            cst[nt] = fmaf(sf, cst[nt], si * tg);
            float h = so * tanh_fast(cst[nt]);
            int u = myu + 2 * nt;
            if (u < HID) {
                float hh = __bfloat162float(__float2bfloat16(h));
                *(__nv_bfloat16*)(&sB[nb][0][myb * BST + koff(u)]) = __float2bfloat16(h);
                *(__nv_bfloat16*)(&sB[nb][1][myb * BST + koff(u)]) = __float2bfloat16(h - hh);
            }
        }

        // ---- publish x(t+1) into next buffer ----
        if (tid < 96) {
            float h0 = __bfloat162float(__float2bfloat16(xv.x));
            float h1 = __bfloat162float(__float2bfloat16(xv.y));
            *(u32*)(&sB[nb][0][bx * BST + koff(30 + 2 * jx)]) = pack_bf16x2(h0, h1);
            *(u32*)(&sB[nb][1][bx * BST + koff(30 + 2 * jx)]) = pack_bf16x2(xv.x - h0, xv.y - h1);
        }

        __syncthreads();
    }

    // ---- fused fc1+fc2 epilogue: h = hi + lo (SEQ even -> buf 0) ----
    for (int idx = tid; idx < NB * OUTD; idx += NTHR) {
        int b = idx / OUTD, o = idx % OUTD;
        float s = g_bv[o];
#pragma unroll
        for (int j = 0; j < HID; j++) {
            float hv = __bfloat162float(*(__nv_bfloat16*)(&sB[0][0][b * BST + koff(j)]))
                     + __bfloat162float(*(__nv_bfloat16*)(&sB[0][1][b * BST + koff(j)]));
            s += hv * g_M[j][o];
        }
        out[(size_t)(bbase + b) * OUTD + o] = s;
    }
}

// ---------------- launch ----------------
extern "C" void kernel_launch(void* const* d_in, const int* in_sizes, int n_in,
                              void* d_out, int out_size) {
    const float* X   = (const float*)d_in[0];
    const float* Wih = (const float*)d_in[1];
    const float* Whh = (const float*)d_in[2];
    const float* bih = (const float*)d_in[3];
    const float* bhh = (const float*)d_in[4];
    const float* W1  = (const float*)d_in[5];
    const float* b1  = (const float*)d_in[6];
    const float* W2  = (const float*)d_in[7];
    const float* b2  = (const float*)d_in[8];

    prep_kernel<<<1, 256>>>(Wih, Whh, bih, bhh, W1, b1, W2, b2);
    lstm_kernel<<<NBLK, NTHR>>>(X, (float*)d_out);
}

// round 15
// speedup vs baseline: 1.1280x; 1.1280x over previous
#include <cuda_runtime.h>
#include <cuda_bf16.h>
#include <cstdint>

#define SEQ   600
#define SEQH  (SEQ / 2)
#define BATCH 4096
#define INP   6
#define HID   30
#define OUTD  61
#define NB    32               // batches per CTA (GEMM M)
#define NBLK  (BATCH / NB)     // 128 CTAs
#define NTHR  512              // 16 warps = 2 domains x 8
#define BST   104              // v-row byte stride in sB (bank-spread, 8B mult)
#define SBB   (NB * BST)       // 3328 B per (buf, term)

typedef unsigned long long ull;
typedef uint32_t u32;

// ---------------- device globals ----------------
__device__ u32  g_Bfrag[8][2][3][2][32][2];  // [wN][nt][kt][term][lane][j]
__device__ float g_M[HID][OUTD];             // fused fc1+fc2
__device__ float g_bv[OUTD];

// ---------------- helpers ----------------
__device__ __forceinline__ float tanh_fast(float x) {
    float r; asm("tanh.approx.f32 %0, %1;" : "=f"(r) : "f"(x)); return r;
}
__device__ __forceinline__ float sigmoid_fast(float x) {
    return fmaf(0.5f, tanh_fast(0.5f * x), 0.5f);
}
__device__ __forceinline__ u32 pack_bf16x2(float lo_k, float hi_k) {
    __nv_bfloat162 p = __floats2bfloat162_rn(lo_k, hi_k);
    return *(u32*)&p;
}
// byte offset of k within one batch's v-row (slot s = kt*4+tig holds pairs (p, p+4))
__device__ __host__ __forceinline__ u32 koff(int k) {
    int p = k >> 1, kt = p >> 3, q = p & 7;
    return (u32)(((kt << 2) + (q & 3)) * 8 + (q >> 2) * 4 + (k & 1) * 2);
}
__device__ __forceinline__ void mma16816(float* d, const u32* a, const u32* b) {
    asm volatile(
        "mma.sync.aligned.m16n8k16.row.col.f32.bf16.bf16.f32 "
        "{%0,%1,%2,%3}, {%4,%5,%6,%7}, {%8,%9}, {%0,%1,%2,%3};"
        : "+f"(d[0]), "+f"(d[1]), "+f"(d[2]), "+f"(d[3])
        : "r"(a[0]), "r"(a[1]), "r"(a[2]), "r"(a[3]), "r"(b[0]), "r"(b[1]));
}

// ---------------- prep kernel ----------------
__device__ __forceinline__ float Wval(const float* Wih, const float* Whh,
                                      const float* bih, const float* bhh, int r, int k) {
    int u = r >> 2, g = r & 3;
    if (u >= HID) return 0.0f;
    if (k < HID)       return Whh[(g * HID + u) * HID + k];
    if (k < HID + INP) return Wih[(g * HID + u) * INP + (k - HID)];
    if (k == 36)       return bih[g * HID + u] + bhh[g * HID + u];
    return 0.0f;
}

__global__ void prep_kernel(const float* __restrict__ Wih, const float* __restrict__ Whh,
                            const float* __restrict__ bih, const float* __restrict__ bhh,
                            const float* __restrict__ W1,  const float* __restrict__ b1,
                            const float* __restrict__ W2,  const float* __restrict__ b2) {
    int tid = threadIdx.x;
    for (int idx = tid; idx < 8 * 2 * 3 * 2 * 32 * 2; idx += blockDim.x) {
        int j    = idx & 1;
        int lane = (idx >> 1) & 31;
        int tm   = (idx >> 6) & 1;
        int kt   = (idx >> 7) % 3;
        int nt   = (idx >> 7) / 3 & 1;
        int w    = idx / (2 * 3 * 2 * 32 * 2);
        int g0 = lane >> 2, tig = lane & 3;
        int r = 16 * w + 8 * nt + g0;
        int k = 2 * tig + 16 * kt + 8 * j;
        float w0 = Wval(Wih, Whh, bih, bhh, r, k);
        float w1 = Wval(Wih, Whh, bih, bhh, r, k + 1);
        float h0 = __bfloat162float(__float2bfloat16(w0));
        float h1 = __bfloat162float(__float2bfloat16(w1));
        u32 v = (tm == 0) ? pack_bf16x2(h0, h1) : pack_bf16x2(w0 - h0, w1 - h1);
        g_Bfrag[w][nt][kt][tm][lane][j] = v;
    }
    for (int idx = tid; idx < HID * OUTD; idx += blockDim.x) {
        int j = idx / OUTD, o = idx % OUTD;
        float s = 0.0f;
        for (int kk = 0; kk < HID; kk++) s += W1[kk * HID + j] * W2[o * HID + kk];
        g_M[j][o] = s;
    }
    for (int o = tid; o < OUTD; o += blockDim.x) {
        float s = b2[o];
        for (int kk = 0; kk < HID; kk++) s += b1[kk] * W2[o * HID + kk];
        g_bv[o] = s;
    }
}

// ---------------- one recurrence step (bt, nb are LITERAL constants at call site) ----------------
struct StepCtx {
    const float* X;
    char (*sB)[2][SBB];          // [buf][term][SBB]
    int dm, g0, tig, odd, myu, myb, barid;
    int xact, bx, jx;            // x-staging role
    size_t xrow;                 // gmem base offset for my x pair (batch part)
    const u32 (*Bf)[3][2][2];    // [nt][kt][tm][j]
};

template <int BT>
__device__ __forceinline__ void lstm_step(const StepCtx& cx, float* cst, int t) {
    const int NBUF = BT ^ 1;
    // prefetch x(t+1)
    float2 xv;
    const int tn = (t + 1 < SEQ) ? t + 1 : t;
    if (cx.xact) xv = *(const float2*)(cx.X + (size_t)tn * (BATCH * INP) + cx.xrow);

    // ---- load A fragments (my m-tile): one LDS.64 = {a_klo, a_khi} ----
    u32 A[3][2][4];
#pragma unroll
    for (int kt = 0; kt < 3; kt++)
#pragma unroll
        for (int tm = 0; tm < 2; tm++) {
            const char* base = cx.sB[BT][tm];
            ull v0 = *(const ull*)(base + (16 * cx.dm + cx.g0) * BST + (kt * 4 + cx.tig) * 8);
            ull v1 = *(const ull*)(base + (16 * cx.dm + cx.g0 + 8) * BST + (kt * 4 + cx.tig) * 8);
            A[kt][tm][0] = (u32)v0;  A[kt][tm][2] = (u32)(v0 >> 32);
            A[kt][tm][1] = (u32)v1;  A[kt][tm][3] = (u32)(v1 >> 32);
        }

    // ---- 18 mma: 2 D tiles (nt), each split into 2 accumulators ----
    float D[2][4], E[2][4];
#pragma unroll
    for (int nt = 0; nt < 2; nt++) {
        D[nt][0] = D[nt][1] = D[nt][2] = D[nt][3] = 0.0f;
        E[nt][0] = E[nt][1] = E[nt][2] = E[nt][3] = 0.0f;
#pragma unroll
        for (int kt = 0; kt < 3; kt++) {
            mma16816(D[nt], A[kt][0], cx.Bf[nt][kt][0]);  // vhi*whi
            mma16816(E[nt], A[kt][0], cx.Bf[nt][kt][1]);  // vhi*wlo
            mma16816(D[nt], A[kt][1], cx.Bf[nt][kt][0]);  // vlo*whi
        }
#pragma unroll
        for (int i = 0; i < 4; i++) D[nt][i] += E[nt][i];
    }

    // ---- epilogue: gates via shfl.xor(1), act, c/h update, h store ----
#pragma unroll
    for (int nt = 0; nt < 2; nt++) {
        float d0 = D[nt][0], d1 = D[nt][1], d2 = D[nt][2], d3 = D[nt][3];
        float s0 = __shfl_xor_sync(0xffffffffu, d0, 1);
        float s1 = __shfl_xor_sync(0xffffffffu, d1, 1);
        float s2 = __shfl_xor_sync(0xffffffffu, d2, 1);
        float s3 = __shfl_xor_sync(0xffffffffu, d3, 1);
        float gi = cx.odd ? s2 : d0;
        float gf = cx.odd ? s3 : d1;
        float gg = cx.odd ? d2 : s0;
        float go = cx.odd ? d3 : s1;
        float si = sigmoid_fast(gi);
        float sf = sigmoid_fast(gf);
        float tg = tanh_fast(gg);
        float so = sigmoid_fast(go);
        cst[nt] = fmaf(sf, cst[nt], si * tg);
        float h = so * tanh_fast(cst[nt]);
        int u = cx.myu + 2 * nt;
        if (u < HID) {
            float hh = __bfloat162float(__float2bfloat16(h));
            *(__nv_bfloat16*)(&cx.sB[NBUF][0][cx.myb * BST + koff(u)]) = __float2bfloat16(h);
            *(__nv_bfloat16*)(&cx.sB[NBUF][1][cx.myb * BST + koff(u)]) = __float2bfloat16(h - hh);
        }
    }

    // ---- publish x(t+1) into next buffer ----
    if (cx.xact) {
        float h0 = __bfloat162float(__float2bfloat16(xv.x));
        float h1 = __bfloat162float(__float2bfloat16(xv.y));
        *(u32*)(&cx.sB[NBUF][0][cx.bx * BST + koff(30 + 2 * cx.jx)]) = pack_bf16x2(h0, h1);
        *(u32*)(&cx.sB[NBUF][1][cx.bx * BST + koff(30 + 2 * cx.jx)]) = pack_bf16x2(xv.x - h0, xv.y - h1);
    }

    // domain-local barrier (256 threads of this m-tile)
    asm volatile("bar.sync %0, 256;" :: "r"(cx.barid) : "memory");
}

// ---------------- main kernel: 3xBF16 mma.sync, 2 desync domains, unroll-2 ----------------
__global__ void __launch_bounds__(NTHR, 1)
lstm_kernel(const float* __restrict__ X, float* __restrict__ out) {
    __shared__ __align__(16) char sB[2][2][SBB];   // 13312 B

    const int tid   = threadIdx.x;
    const int lane  = tid & 31;
    const int wid   = tid >> 5;            // 0..15
    const int wN    = wid & 7;             // gate-row group
    const int dm    = wid >> 3;            // domain / m-tile
    const int ltid  = tid & 255;           // tid within domain
    const int g0    = lane >> 2;
    const int tig   = lane & 3;
    const int bbase = blockIdx.x * NB;

    // persistent weight fragments
    u32 Bf[2][3][2][2];
#pragma unroll
    for (int nt = 0; nt < 2; nt++)
#pragma unroll
        for (int kt = 0; kt < 3; kt++)
#pragma unroll
            for (int tm = 0; tm < 2; tm++) {
                Bf[nt][kt][tm][0] = g_Bfrag[wN][nt][kt][tm][lane][0];
                Bf[nt][kt][tm][1] = g_Bfrag[wN][nt][kt][tm][lane][1];
            }

    // init: zero both buffers, set bias col (k=36 -> byte 80)
    for (int i = tid; i < 2 * 2 * SBB / 4; i += NTHR) ((u32*)sB)[i] = 0u;
    __syncthreads();
    if (tid < NB) {
        *(u32*)(&sB[0][0][tid * BST + 80]) = 0x00003F80u;   // {bf16(1.0), 0}
        *(u32*)(&sB[1][0][tid * BST + 80]) = 0x00003F80u;
    }
    // x staging role: first 48 threads of each domain cover its 16 batches x 3 pairs
    const int xact = (ltid < 48);
    const int bx   = 16 * dm + (ltid & 15);
    const int jx   = (ltid >> 4) & 3;       // 0..2 when active
    const size_t xrow = (size_t)(bbase + bx) * INP + 2 * jx;
    if (xact) {
        float2 xv = *(const float2*)(X + xrow);
        float h0 = __bfloat162float(__float2bfloat16(xv.x));
        float h1 = __bfloat162float(__float2bfloat16(xv.y));
        *(u32*)(&sB[0][0][bx * BST + koff(30 + 2 * jx)]) = pack_bf16x2(h0, h1);
        *(u32*)(&sB[0][1][bx * BST + koff(30 + 2 * jx)]) = pack_bf16x2(xv.x - h0, xv.y - h1);
    }
    __syncthreads();

    StepCtx cx;
    cx.X = X; cx.sB = sB;
    cx.dm = dm; cx.g0 = g0; cx.tig = tig; cx.odd = tig & 1;
    cx.myu = 4 * wN + (tig >> 1);
    cx.myb = g0 + 8 * (tig & 1) + 16 * dm;
    cx.barid = 1 + dm;
    cx.xact = xact; cx.bx = bx; cx.jx = jx; cx.xrow = xrow;
    cx.Bf = Bf;

    float cst[2] = {0.0f, 0.0f};

#pragma unroll 1
    for (int th = 0; th < SEQH; ++th) {
        lstm_step<0>(cx, cst, 2 * th);      // buf0 -> buf1
        lstm_step<1>(cx, cst, 2 * th + 1);  // buf1 -> buf0
    }

    // ---- fused fc1+fc2 epilogue (final h in buf 0) ----
    __syncthreads();
    for (int idx = tid; idx < NB * OUTD; idx += NTHR) {
        int b = idx / OUTD, o = idx % OUTD;
        float s = g_bv[o];
#pragma unroll
        for (int j = 0; j < HID; j++) {
            float hv = __bfloat162float(*(__nv_bfloat16*)(&sB[0][0][b * BST + koff(j)]))
                     + __bfloat162float(*(__nv_bfloat16*)(&sB[0][1][b * BST + koff(j)]));
            s += hv * g_M[j][o];
        }
        out[(size_t)(bbase + b) * OUTD + o] = s;
    }
}

// ---------------- launch ----------------
extern "C" void kernel_launch(void* const* d_in, const int* in_sizes, int n_in,
                              void* d_out, int out_size) {
    const float* X   = (const float*)d_in[0];
    const float* Wih = (const float*)d_in[1];
    const float* Whh = (const float*)d_in[2];
    const float* bih = (const float*)d_in[3];
    const float* bhh = (const float*)d_in[4];
    const float* W1  = (const float*)d_in[5];
    const float* b1  = (const float*)d_in[6];
    const float* W2  = (const float*)d_in[7];
    const float* b2  = (const float*)d_in[8];

    prep_kernel<<<1, 256>>>(Wih, Whh, bih, bhh, W1, b1, W2, b2);
    lstm_kernel<<<NBLK, NTHR>>>(X, (float*)d_out);
}